// round 5
// baseline (speedup 1.0000x reference)
#include <cuda_runtime.h>
#include <stdint.h>
#include <math.h>

#define BB 512
#define EE 256
#define HH 512
#define GG 1536
#define VV 32000
#define SS 256
#define OUT_LP_OFF (BB*SS) // 131072

#define NBLK 148
#define NTHR 256
#define NCH 4              // v-chunks per row in sampling phases
#define CHSZ (VV / NCH)    // 8000

// ---------------- scratch (device globals; no allocation allowed) ----------------
__device__ float g_h[BB * HH];
__device__ float g_gi[BB * GG];
__device__ float g_gh[BB * GG];
__device__ float g_logits[BB * VV];
__device__ int   g_sampled[BB];
__device__ float g_pm[BB * NCH];      // partial row max per (row, chunk)
__device__ float g_ps[BB * NCH];      // partial scaled expsum per (row, chunk)
__device__ float g_bv[BB * NCH];      // partial best value per (row, chunk)
__device__ int   g_bi[BB * NCH];      // partial best index
__device__ unsigned g_bar;

// ---------------- JAX threefry2x32 (exact) ----------------
__device__ __forceinline__ void tf2x32(uint32_t k0, uint32_t k1,
                                       uint32_t x0, uint32_t x1,
                                       uint32_t &o0, uint32_t &o1) {
  uint32_t k2 = k0 ^ k1 ^ 0x1BD11BDAu;
#define ROTL(x, r) (((x) << (r)) | ((x) >> (32 - (r))))
#define RND(r) { x0 += x1; x1 = ROTL(x1, r); x1 ^= x0; }
  x0 += k0; x1 += k1;
  RND(13) RND(15) RND(26) RND(6)
  x0 += k1; x1 += k2 + 1u;
  RND(17) RND(29) RND(16) RND(24)
  x0 += k2; x1 += k0 + 2u;
  RND(13) RND(15) RND(26) RND(6)
  x0 += k0; x1 += k1 + 3u;
  RND(17) RND(29) RND(16) RND(24)
  x0 += k1; x1 += k2 + 4u;
  RND(13) RND(15) RND(26) RND(6)
  x0 += k2; x1 += k0 + 5u;
#undef RND
#undef ROTL
  o0 = x0; o1 = x1;
}

// -------- partitionable-mode derivations (jax_threefry_partitionable=True) -------
// split(key, n): key_i = (o0, o1) of threefry(key, (0, i))
__device__ __forceinline__ void split_key(uint32_t k0, uint32_t k1, uint32_t i,
                                          uint32_t &n0, uint32_t &n1) {
  tf2x32(k0, k1, 0u, i, n0, n1);
}

// random_bits(key, 32, shape)[n] = o0 ^ o1 of threefry(key, (0, n)) (n = flat idx)
__device__ __forceinline__ uint32_t rbits32(uint32_t k0, uint32_t k1, uint32_t n) {
  uint32_t o0, o1;
  tf2x32(k0, k1, 0u, n, o0, o1);
  return o0 ^ o1;
}

__device__ __forceinline__ float bits_to_uniform(uint32_t bits) {
  return __uint_as_float((bits >> 9) | 0x3f800000u) - 1.0f;
}

__device__ __forceinline__ float gumbel_from_bits(uint32_t bits) {
  float u = bits_to_uniform(bits);
  if (u == 0.0f) u = 1.17549435e-38f;   // uniform(minval=tiny): 0 -> tiny
  return -logf(-logf(u));               // accurate: argmax-critical
}

// ---------------- software grid barrier (monotonic target) ----------------
__device__ __forceinline__ void gridbar(unsigned &target) {
  target += NBLK;
  __syncthreads();
  if (threadIdx.x == 0) {
    __threadfence();
    atomicAdd(&g_bar, 1u);
    unsigned v;
    do {
      asm volatile("ld.acquire.gpu.u32 %0, [%1];" : "=r"(v) : "l"(&g_bar) : "memory");
    } while (v < target);
  }
  __syncthreads();
}

// ---------------- 64x128 fp32 TN GEMM tile ----------------
__device__ __forceinline__ void gemm_tile(
    const float *__restrict__ Abase, int aStride, const int *gather,
    int Krun, const float *__restrict__ W, int wStride,
    const float *__restrict__ bias, float *__restrict__ C, int ldc,
    int bm, int bn, float *sm) {
  float (*As)[68]  = reinterpret_cast<float (*)[68]>(sm);
  float (*Ws)[132] = reinterpret_cast<float (*)[132]>(sm + 16 * 68);
  const int tid = threadIdx.x;
  const int tx = tid & 15;
  const int ty = tid >> 4;
  const int lm = tid >> 2;
  const int lk = (tid & 3) * 4;

  const int arowi = gather ? gather[bm + lm] : (bm + lm);
  const float *arow  = Abase + (size_t)arowi * aStride;
  const float *wrow0 = W + (size_t)(bn + lm) * wStride;
  const float *wrow1 = W + (size_t)(bn + 64 + lm) * wStride;

  float acc[4][8];
#pragma unroll
  for (int i = 0; i < 4; i++)
#pragma unroll
    for (int j = 0; j < 8; j++) acc[i][j] = 0.0f;

  for (int k0 = 0; k0 < Krun; k0 += 16) {
    float4 av = *reinterpret_cast<const float4 *>(arow + k0 + lk);
    float4 w0 = *reinterpret_cast<const float4 *>(wrow0 + k0 + lk);
    float4 w1 = *reinterpret_cast<const float4 *>(wrow1 + k0 + lk);
    As[lk + 0][lm] = av.x; As[lk + 1][lm] = av.y;
    As[lk + 2][lm] = av.z; As[lk + 3][lm] = av.w;
    Ws[lk + 0][lm] = w0.x; Ws[lk + 1][lm] = w0.y;
    Ws[lk + 2][lm] = w0.z; Ws[lk + 3][lm] = w0.w;
    Ws[lk + 0][64 + lm] = w1.x; Ws[lk + 1][64 + lm] = w1.y;
    Ws[lk + 2][64 + lm] = w1.z; Ws[lk + 3][64 + lm] = w1.w;
    __syncthreads();
#pragma unroll
    for (int kk = 0; kk < 16; kk++) {
      float4 a  = *reinterpret_cast<const float4 *>(&As[kk][ty * 4]);
      float4 b0 = *reinterpret_cast<const float4 *>(&Ws[kk][tx * 4]);
      float4 b1 = *reinterpret_cast<const float4 *>(&Ws[kk][64 + tx * 4]);
      float a4[4] = {a.x, a.y, a.z, a.w};
      float b8[8] = {b0.x, b0.y, b0.z, b0.w, b1.x, b1.y, b1.z, b1.w};
#pragma unroll
      for (int i = 0; i < 4; i++)
#pragma unroll
        for (int j = 0; j < 8; j++)
          acc[i][j] = fmaf(a4[i], b8[j], acc[i][j]);
    }
    __syncthreads();
  }

#pragma unroll
  for (int i = 0; i < 4; i++) {
    int row = bm + ty * 4 + i;
    int base = row * ldc;
#pragma unroll
    for (int j = 0; j < 4; j++) {
      int c0 = bn + tx * 4 + j;
      int c1 = bn + 64 + tx * 4 + j;
      C[base + c0] = acc[i][j] + bias[c0];
      C[base + c1] = acc[i][4 + j] + bias[c1];
    }
  }
}

// per-row max + log(sum) from NCH chunk partials.
// lse rounding shifts all of a row's candidates uniformly -> argmax invariant.
__device__ __forceinline__ void row_stats(int row, float &m, float &l) {
  float M = g_pm[row * NCH + 0];
#pragma unroll
  for (int c = 1; c < NCH; c++) M = fmaxf(M, g_pm[row * NCH + c]);
  float s = 0.0f;
#pragma unroll
  for (int c = 0; c < NCH; c++)
    s += g_ps[row * NCH + c] * __expf(g_pm[row * NCH + c] - M);
  m = M;
  l = logf(s);
}

// ---------------- init kernel (resets barrier/state each replay) ----------------
__global__ void init_kernel() {
  int i = blockIdx.x * blockDim.x + threadIdx.x;
  if (i == 0) g_bar = 0u;
  if (i < BB) g_sampled[i] = 0;        // start token id 0
  if (i < BB * HH) g_h[i] = 0.0f;
}

// ---------------- the whole 256-step loop as one persistent kernel ----------------
__global__ void __launch_bounds__(NTHR)
actor_kernel(const float *__restrict__ embedding,
             const float *__restrict__ w_ih, const float *__restrict__ w_hh,
             const float *__restrict__ b_ih, const float *__restrict__ b_hh,
             const float *__restrict__ w_out, const float *__restrict__ b_out,
             float *__restrict__ out) {
  __shared__ __align__(16) float sm[16 * 68 + 16 * 132];  // 12.8 KB, reused per phase
  const int tid = threadIdx.x;
  unsigned bar_target = 0;

  for (int t = 0; t < SS; t++) {
    // ---- Phase A: gi = emb[sampled] @ w_ih^T + b_ih ; gh = h @ w_hh^T + b_hh ----
    for (int tile = blockIdx.x; tile < 192; tile += NBLK) {
      if (tile < 96) {
        int mt = tile / 12, nt = tile % 12;
        gemm_tile(embedding, EE, g_sampled, EE, w_ih, EE, b_ih,
                  g_gi, GG, mt * 64, nt * 128, sm);
      } else {
        int t2 = tile - 96;
        int mt = t2 / 12, nt = t2 % 12;
        gemm_tile(g_h, HH, nullptr, HH, w_hh, HH, b_hh,
                  g_gh, GG, mt * 64, nt * 128, sm);
      }
    }
    gridbar(bar_target);

    // ---- Phase B: GRU combine (h updated in place) ----
    for (int i = blockIdx.x * NTHR + tid; i < BB * HH; i += NBLK * NTHR) {
      int b = i >> 9, j = i & 511;
      const float *gi = g_gi + b * GG;
      const float *gh = g_gh + b * GG;
      float ir = gi[j],           hr = gh[j];
      float iz = gi[j + HH],      hz = gh[j + HH];
      float in_ = gi[j + 2 * HH], hn = gh[j + 2 * HH];
      float r = 1.0f / (1.0f + expf(-(ir + hr)));
      float z = 1.0f / (1.0f + expf(-(iz + hz)));
      float n = tanhf(in_ + r * hn);
      float hp = g_h[i];
      g_h[i] = (1.0f - z) * n + z * hp;
    }
    gridbar(bar_target);

    // ---- Phase C: logits = h @ w_out^T + b_out ----
    for (int tile = blockIdx.x; tile < 2000; tile += NBLK) {
      int mt = tile / 250, nt = tile % 250;
      gemm_tile(g_h, HH, nullptr, HH, w_out, HH, b_out,
                g_logits, VV, mt * 64, nt * 128, sm);
    }
    gridbar(bar_target);

    // ---- Phase D1: per (row, chunk) online max + expsum partials ----
    {
      float *rm = sm;
      float *rs = sm + 256;
      for (int u = blockIdx.x; u < BB * NCH; u += NBLK) {
        int row = u >> 2, c = u & (NCH - 1);
        int v0 = c * CHSZ, v1 = v0 + CHSZ;
        const float *lr = g_logits + row * VV;
        float m = -3.402823466e38f, s = 0.0f;
        for (int v = v0 + tid; v < v1; v += NTHR) {
          float x = lr[v];
          if (x > m) { s = s * __expf(m - x) + 1.0f; m = x; }
          else        s += __expf(x - m);
        }
        rm[tid] = m; rs[tid] = s;
        __syncthreads();
        for (int str = 128; str > 0; str >>= 1) {
          if (tid < str) {
            float m1 = rm[tid], s1 = rs[tid];
            float m2 = rm[tid + str], s2 = rs[tid + str];
            float M = fmaxf(m1, m2);
            rm[tid] = M;
            rs[tid] = s1 * __expf(m1 - M) + s2 * __expf(m2 - M);
          }
          __syncthreads();
        }
        if (tid == 0) { g_pm[u] = rm[0]; g_ps[u] = rs[0]; }
        __syncthreads();
      }
    }
    gridbar(bar_target);

    // ---- Phase D2: gumbel argmax partials per (row, chunk) ----
    {
      // keys = split(key(42), 256); key_t = threefry(key, (0, t))  [foldlike]
      uint32_t kt0, kt1;
      split_key(0u, 42u, (uint32_t)t, kt0, kt1);
      // k_eps, k_gum = split(key_t, 2) -> counters (0,0) and (0,1)
      uint32_t ke0, ke1, kg0, kg1;
      split_key(kt0, kt1, 0u, ke0, ke1);
      split_key(kt0, kt1, 1u, kg0, kg1);

      float tf = (float)t;
      float eps = 0.05f + 0.95f * expf((-4.0f * tf) / 10000.0f);
      const float NEG_LOGV = -10.373491181781864f;  // -float32(log(32000))

      float *sv = sm;                   // [256]
      int   *si = (int *)(sm + 256);    // [256]

      for (int u = blockIdx.x; u < BB * NCH; u += NBLK) {
        int row = u >> 2, c = u & (NCH - 1);
        int v0 = c * CHSZ, v1 = v0 + CHSZ;

        // eps draw for this row: uniform(k_eps, (512,))[row] = xor-fold bits
        bool draw = (eps >= bits_to_uniform(rbits32(ke0, ke1, (uint32_t)row)));

        float m, l;
        row_stats(row, m, l);
        const float *lr = g_logits + row * VV;

        float bv = -3.402823466e38f;
        int bi = 0;
        for (int v = v0 + tid; v < v1; v += NTHR) {
          // gumbel(k_gum, (B,V)) flat idx n = row*V + v, bits = o0^o1
          uint32_t bits = rbits32(kg0, kg1, (uint32_t)(row * VV + v));
          float g = gumbel_from_bits(bits);
          float val = draw ? (NEG_LOGV + g) : (((lr[v] - m) - l) + g);
          if (val > bv) { bv = val; bi = v; }
        }
        sv[tid] = bv; si[tid] = bi;
        __syncthreads();
        for (int str = 128; str > 0; str >>= 1) {
          if (tid < str) {
            float v2 = sv[tid + str]; int i2 = si[tid + str];
            float v1f = sv[tid];      int i1 = si[tid];
            if (v2 > v1f || (v2 == v1f && i2 < i1)) { sv[tid] = v2; si[tid] = i2; }
          }
          __syncthreads();
        }
        if (tid == 0) { g_bv[u] = sv[0]; g_bi[u] = si[0]; }
        __syncthreads();
      }
    }
    gridbar(bar_target);

    // ---- Phase E: finalize (block 0): merge chunks, write sampled + out ----
    if (blockIdx.x == 0) {
      for (int row = tid; row < BB; row += NTHR) {
        float bv = g_bv[row * NCH + 0];
        int   bi = g_bi[row * NCH + 0];
#pragma unroll
        for (int c = 1; c < NCH; c++) {
          float v2 = g_bv[row * NCH + c];
          int   i2 = g_bi[row * NCH + c];
          if (v2 > bv) { bv = v2; bi = i2; }   // ascending chunks => first-index ties kept
        }
        float m, l;
        row_stats(row, m, l);
        float lp = (g_logits[row * VV + bi] - m) - l;
        g_sampled[row] = bi;
        out[row * SS + t] = (float)bi;
        out[OUT_LP_OFF + row * SS + t] = lp;
      }
    }
    gridbar(bar_target);
  }
}

// ---------------- launch ----------------
extern "C" void kernel_launch(void *const *d_in, const int *in_sizes, int n_in,
                              void *d_out, int out_size) {
  const float *embedding = (const float *)d_in[0];  // [V,E]
  const float *w_ih      = (const float *)d_in[1];  // [3H,E]
  const float *w_hh      = (const float *)d_in[2];  // [3H,H]
  const float *b_ih      = (const float *)d_in[3];  // [3H]
  const float *b_hh      = (const float *)d_in[4];  // [3H]
  const float *w_out     = (const float *)d_in[5];  // [V,H]
  const float *b_out     = (const float *)d_in[6];  // [V]
  float *out = (float *)d_out;

  init_kernel<<<512, 512>>>();
  actor_kernel<<<NBLK, NTHR>>>(embedding, w_ih, w_hh, b_ih, b_hh,
                               w_out, b_out, out);
}